// round 16
// baseline (speedup 1.0000x reference)
#include <cuda_runtime.h>
#include <cstdint>

typedef unsigned long long ull;

#define BATCH 8192
#define TSTEPS 64
#define NCTA 128
#define THREADS 512

__device__ float g_x2[BATCH * 128];
__device__ float g_zc[BATCH * 128];
__device__ float g_eWT[128 * 384];    // enc Whh^T [k][j]  (r|z|n)
__device__ float g_dWT2[128 * 512];   // dec t>=1: [k][ (Wih+Whh)_rz | Wih_n | Whh_n ]
__device__ float g_dW0[128 * 512];    // dec t==0: [k][ Whh_rz | 0 | Whh_n ]

// smem layout (float offsets)
// enc phase: H0 0..8191, H1 8192..16383, BUF 16384..40959 (2x12288),
//            WI 40960..52095, X 52096..53951, B 53952..54975
// dec phase: HD0 0..16383 (dup h), dec bufs 16384..32767 (2x8192),
//            HD1 32768..49151 (dup h), B unchanged
constexpr int O_H0   = 0;
constexpr int O_H1   = 8192;
constexpr int O_BUF0 = 16384;
constexpr int O_DB   = 16384;    // dec buffers (2 x 8192)
constexpr int O_HD1  = 32768;    // dec dup-h pong
constexpr int O_WI   = 40960;
constexpr int O_X    = 52096;
constexpr int O_B    = 53952;
constexpr int MBAR_BYTE  = 55488 * 4;
constexpr int SMEM_BYTES = MBAR_BYTE + 32;
constexpr int NSEQ = 512 + 1024;         // enc 64*2*4, dec 64*2*8
constexpr int CONV_SMEM = (8*1728 + 3888 + 2048 + 8*144) * 4;
constexpr int FC_SMEM   = 32768 * 4;

__device__ __forceinline__ ull pk2(float a, float b) {
    ull r; asm("mov.b64 %0, {%1,%2};" : "=l"(r) : "f"(a), "f"(b)); return r;
}
__device__ __forceinline__ void upk2(ull v, float& a, float& b) {
    asm("mov.b64 {%0,%1}, %2;" : "=f"(a), "=f"(b) : "l"(v));
}
__device__ __forceinline__ void fma2(ull& d, ull a, ull b) {
    asm("fma.rn.f32x2 %0, %1, %2, %0;" : "+l"(d) : "l"(a), "l"(b));
}
__device__ __forceinline__ float sigf(float x)     { return 1.0f / (1.0f + __expf(-x)); }
__device__ __forceinline__ float tanhfast(float x) { return 2.0f / (1.0f + __expf(-2.0f * x)) - 1.0f; }
__device__ __forceinline__ uint32_t smem_u32(const void* p) {
    uint32_t a;
    asm("{ .reg .u64 t; cvta.to.shared.u64 t, %1; cvt.u32.u64 %0, t; }" : "=r"(a) : "l"(p));
    return a;
}
__device__ __forceinline__ void mbar_init(uint32_t bar, uint32_t cnt) {
    asm volatile("mbarrier.init.shared.b64 [%0], %1;" :: "r"(bar), "r"(cnt) : "memory");
}
__device__ __forceinline__ void mbar_arrive(uint32_t bar) {
    asm volatile("mbarrier.arrive.release.cta.shared::cta.b64 _, [%0];" :: "r"(bar) : "memory");
}
__device__ __forceinline__ void wait_par(uint32_t bar, uint32_t parity) {
    asm volatile(
        "{\n\t.reg .pred P;\n\t"
        "WL_%=:\n\t"
        "mbarrier.try_wait.parity.acquire.cta.shared::cta.b64 P, [%0], %1, 0x989680;\n\t"
        "@P bra.uni WD_%=;\n\t"
        "bra.uni WL_%=;\n\t"
        "WD_%=:\n\t}"
        :: "r"(bar), "r"(parity) : "memory");
}
// seq -> (dst, src, bytes): enc s<512 -> 48KB into O_BUF0 region;
// dec -> 32KB into O_DB region (disjoint from HD1).
__device__ __forceinline__ void issue_chunk(int s, uint32_t smb) {
    uint32_t dst;
    uint32_t bar = smb + MBAR_BYTE + (s & 1) * 8;
    const float* src;
    uint32_t bytes;
    if (s < 512) {
        dst = smb + (uint32_t)(O_BUF0 + (s & 1) * 12288) * 4;
        src = g_eWT + (size_t)(s & 3) * 32 * 384;
        bytes = 49152;
    } else {
        int d = s - 512;
        dst = smb + (uint32_t)(O_DB + (s & 1) * 8192) * 4;
        src = ((d >> 4) == 0 ? g_dW0 : g_dWT2) + (size_t)(d & 7) * 16 * 512;
        bytes = 32768;
    }
    asm volatile("mbarrier.arrive.expect_tx.shared.b64 _, [%0], %1;"
                 :: "r"(bar), "r"(bytes) : "memory");
    asm volatile("cp.async.bulk.shared::cluster.global.mbarrier::complete_tx::bytes "
                 "[%0], [%1], %2, [%3];"
                 :: "r"(dst), "l"(src), "r"(bytes), "r"(bar) : "memory");
}
__device__ __forceinline__ void release_chunk(int s, uint32_t smb, int tid) {
    uint32_t ebar = smb + MBAR_BYTE + 16 + (s & 1) * 8;
    if ((tid & 31) == 0) mbar_arrive(ebar);
    if (tid == 0 && s + 2 < NSEQ) {
        wait_par(ebar, (uint32_t)((s >> 1) & 1));
        issue_chunk(s + 2, smb);
    }
}

// enc fragment (R8 verbatim): w cols {0,128,256} -> acc {0,1,S2}. Row width WW.
template <int KN, int WW, int S2>
__device__ __forceinline__ void fragE(const float* __restrict__ w,
                                      const float* __restrict__ op,
                                      ull (&acc)[4][4], int col2, int prow)
{
#pragma unroll 8
    for (int k = 0; k < KN; ++k) {
        float4 hv = *(const float4*)(op + k * 64 + prow);
        ull h0 = pk2(hv.x, hv.x), h1 = pk2(hv.y, hv.y);
        ull h2 = pk2(hv.z, hv.z), h3 = pk2(hv.w, hv.w);
        ull w0 = *(const ull*)(w + k * WW + col2);
        ull w1 = *(const ull*)(w + k * WW + 128 + col2);
        ull w2 = *(const ull*)(w + k * WW + 256 + col2);
        fma2(acc[0][0], h0, w0); fma2(acc[0][1], h1, w0);
        fma2(acc[0][2], h2, w0); fma2(acc[0][3], h3, w0);
        fma2(acc[1][0], h0, w1); fma2(acc[1][1], h1, w1);
        fma2(acc[1][2], h2, w1); fma2(acc[1][3], h3, w1);
        fma2(acc[S2][0], h0, w2); fma2(acc[S2][1], h1, w2);
        fma2(acc[S2][2], h2, w2); fma2(acc[S2][3], h3, w2);
    }
}
// dec fragment with DUP-h operand: rows pre-duplicated, zero packing MOVs.
// hd layout [k][2*64]; thread's 4 rows at prow2 = 2*prow -> 2 x LDS.128.
template <int KN>
__device__ __forceinline__ void fragDdup(const float* __restrict__ w,
                                         const float* __restrict__ hd,
                                         ull (&acc)[4][4], int col2, int prow2)
{
#pragma unroll 8
    for (int k = 0; k < KN; ++k) {
        ulonglong2 ha = *(const ulonglong2*)(hd + k * 128 + prow2);      // rows r,r+1
        ulonglong2 hb = *(const ulonglong2*)(hd + k * 128 + prow2 + 4);  // rows r+2,r+3
#pragma unroll
        for (int s = 0; s < 4; ++s) {
            ull wv = *(const ull*)(w + k * 512 + s * 128 + col2);
            fma2(acc[s][0], ha.x, wv); fma2(acc[s][1], ha.y, wv);
            fma2(acc[s][2], hb.x, wv); fma2(acc[s][3], hb.y, wv);
        }
    }
}

// enc epilogue (R8 verbatim): normal h layout
__device__ __forceinline__ void gru_epi(ull (&acc)[4][4], const float* __restrict__ hc,
                                        float* __restrict__ hn, int j, int prow)
{
#pragma unroll
    for (int rr = 0; rr < 4; ++rr) {
        int r = prow + rr;
        float r0, r1, z0, z1, xn0, xn1, hn0, hn1;
        upk2(acc[0][rr], r0, r1); upk2(acc[1][rr], z0, z1);
        upk2(acc[2][rr], xn0, xn1); upk2(acc[3][rr], hn0, hn1);
        float rg0 = sigf(r0), rg1 = sigf(r1);
        float zg0 = sigf(z0), zg1 = sigf(z1);
        float n0 = tanhfast(xn0 + rg0 * hn0), n1 = tanhfast(xn1 + rg1 * hn1);
        float hp0 = hc[j * 64 + r], hp1 = hc[(j + 1) * 64 + r];
        hn[j * 64 + r]       = (1.0f - zg0) * n0 + zg0 * hp0;
        hn[(j + 1) * 64 + r] = (1.0f - zg1) * n1 + zg1 * hp1;
    }
}
// dec epilogue: read h_prev from dup buffer, write dup pairs
__device__ __forceinline__ void gru_epi_dup(ull (&acc)[4][4], const float* __restrict__ hdc,
                                            float* __restrict__ hdn, int j, int prow2)
{
#pragma unroll
    for (int rr = 0; rr < 4; ++rr) {
        int r2 = prow2 + 2 * rr;
        float r0, r1, z0, z1, xn0, xn1, hn0, hn1;
        upk2(acc[0][rr], r0, r1); upk2(acc[1][rr], z0, z1);
        upk2(acc[2][rr], xn0, xn1); upk2(acc[3][rr], hn0, hn1);
        float rg0 = sigf(r0), rg1 = sigf(r1);
        float zg0 = sigf(z0), zg1 = sigf(z1);
        float n0 = tanhfast(xn0 + rg0 * hn0), n1 = tanhfast(xn1 + rg1 * hn1);
        float hp0 = hdc[j * 128 + r2], hp1 = hdc[(j + 1) * 128 + r2];
        float v0 = (1.0f - zg0) * n0 + zg0 * hp0;
        float v1 = (1.0f - zg1) * n1 + zg1 * hp1;
        float2 d0; d0.x = v0; d0.y = v0;
        float2 d1; d1.x = v1; d1.y = v1;
        *(float2*)(hdn + j * 128 + r2)       = d0;
        *(float2*)(hdn + (j + 1) * 128 + r2) = d1;
    }
}

// one-shot weight prep (R8 verbatim)
__global__ void wt_k(const float* __restrict__ eWhh,
                     const float* __restrict__ dWih, const float* __restrict__ dWhh)
{
    int i = blockIdx.x * 256 + threadIdx.x;
    if (i < 128 * 384) {
        int k = i / 384, j = i % 384;
        g_eWT[i] = eWhh[(size_t)j * 128 + k];
    } else if (i < 128 * 384 + 128 * 512) {
        int e = i - 128 * 384;
        int k = e / 512, j = e % 512;
        float v, v0;
        if (j < 256)      { v = dWih[(size_t)j * 128 + k] + dWhh[(size_t)j * 128 + k];
                            v0 = dWhh[(size_t)j * 128 + k]; }
        else if (j < 384) { v = dWih[(size_t)j * 128 + k];  v0 = 0.0f; }
        else              { v = dWhh[(size_t)(j - 128) * 128 + k];
                            v0 = dWhh[(size_t)(j - 128) * 128 + k]; }
        g_dWT2[e] = v;
        g_dW0[e]  = v0;
    }
}

// ============ persistent recurrence: 128 CTAs x 64 batch rows ============
__global__ void __launch_bounds__(THREADS, 1)
recur_k(const float* __restrict__ lin, const float* __restrict__ eWih,
        const float* __restrict__ ebih, const float* __restrict__ ebhh,
        const float* __restrict__ dbih, const float* __restrict__ dbhh,
        const float* __restrict__ disw, const float* __restrict__ disb,
        const float* __restrict__ vw,   const float* __restrict__ vb,
        float* __restrict__ out)
{
    extern __shared__ float sm[];
    const uint32_t smb = smem_u32(sm);
    const int tid  = threadIdx.x;
    const int rb   = blockIdx.x * 64;
    const int rg   = tid & 7;          // row group of 4
    const int col2 = 2 * (tid >> 3);   // feature pair

    for (int i = tid; i < 8192; i += THREADS) sm[O_H0 + i] = 0.0f;
    // fused biases: [r_sum, z_sum, xn(bih_n), hn(bhh_n)] per net
    for (int i = tid; i < 128; i += THREADS) {
        sm[O_B + i]       = ebih[i]       + ebhh[i];
        sm[O_B + 128 + i] = ebih[128 + i] + ebhh[128 + i];
        sm[O_B + 256 + i] = ebih[256 + i];
        sm[O_B + 384 + i] = ebhh[256 + i];
        sm[O_B + 512 + i] = dbih[i]       + dbhh[i];
        sm[O_B + 640 + i] = dbih[128 + i] + dbhh[128 + i];
        sm[O_B + 768 + i] = dbih[256 + i];
        sm[O_B + 896 + i] = dbhh[256 + i];
    }
    for (int i = tid; i < 29 * 384; i += THREADS) {
        int k = i / 384, j = i % 384;
        sm[O_WI + k * 384 + j] = eWih[(size_t)j * 29 + k];
    }
    if (tid == 0) {
        mbar_init(smb + MBAR_BYTE,      1);   // full0
        mbar_init(smb + MBAR_BYTE + 8,  1);   // full1
        mbar_init(smb + MBAR_BYTE + 16, 16);  // empty0
        mbar_init(smb + MBAR_BYTE + 24, 16);  // empty1
    }
    __syncthreads();
    if (tid == 0) {
        asm volatile("fence.proxy.async.shared::cta;" ::: "memory");
        issue_chunk(0, smb); issue_chunk(1, smb);
    }

    float* hc = sm + O_H0;
    float* hn = sm + O_H1;
    int seq = 0;

    // -------- encoder (R8 verbatim) --------
    for (int t = 0; t < TSTEPS; ++t) {
        __syncthreads();
        for (int i = tid; i < 64 * 29; i += THREADS) {
            int r = i / 29, k = i % 29;
            sm[O_X + k * 64 + r] = lin[(size_t)(rb + r) * 1856 + (size_t)t * 29 + k];
        }
        __syncthreads();
#pragma unroll 1
        for (int pass = 0; pass < 2; ++pass) {
            const int prow = pass * 32 + rg * 4;
            ull acc[4][4];
#pragma unroll
            for (int s = 0; s < 4; ++s) {
                ull bv = *(const ull*)(sm + O_B + s * 128 + col2);
#pragma unroll
                for (int rr = 0; rr < 4; ++rr) acc[s][rr] = bv;
            }
            fragE<29, 384, 2>(sm + O_WI, sm + O_X, acc, col2, prow);
#pragma unroll 1
            for (int kc = 0; kc < 4; ++kc) {
                const float* buf = sm + O_BUF0 + (seq & 1) * 12288;
                wait_par(smb + MBAR_BYTE + (seq & 1) * 8, (seq >> 1) & 1);
                fragE<32, 384, 3>(buf, hc + kc * 32 * 64, acc, col2, prow);
                release_chunk(seq, smb, tid);
                ++seq;
            }
            gru_epi(acc, hc, hn, col2, prow);
        }
        float* tp = hc; hc = hn; hn = tp;
    }

    // -------- transition: expand final h (normal, in hc) to dup format in HD0 --------
    {
        __syncthreads();   // last epi writes visible
        float tv[16];
#pragma unroll
        for (int i = 0; i < 16; ++i) tv[i] = hc[i * 512 + tid];
        __syncthreads();   // all reads done before HD0 overwrite
        float* hd0 = sm;   // HD0 = 0..16383
#pragma unroll
        for (int i = 0; i < 16; ++i) {
            int idx = i * 512 + tid;
            int k = idx >> 6, r = idx & 63;
            float2 d2; d2.x = tv[i]; d2.y = tv[i];
            *(float2*)(hd0 + k * 128 + 2 * r) = d2;
        }
        // no sync needed here: dec loop starts with __syncthreads()
    }

    float* hdc = sm;            // HD0
    float* hdn = sm + O_HD1;    // HD1

    // -------- decoder (dup-h operand; t=0 streams g_dW0) --------
    for (int t = 0; t < TSTEPS; ++t) {
        __syncthreads();   // prev epi/transition writes done
#pragma unroll 1
        for (int pass = 0; pass < 2; ++pass) {
            const int prow2 = pass * 64 + rg * 8;   // dup row offset
            ull acc[4][4];
#pragma unroll
            for (int s = 0; s < 4; ++s) {
                ull bv = *(const ull*)(sm + O_B + 512 + s * 128 + col2);
#pragma unroll
                for (int rr = 0; rr < 4; ++rr) acc[s][rr] = bv;
            }
#pragma unroll 1
            for (int kc = 0; kc < 8; ++kc) {
                const float* buf = sm + O_DB + (seq & 1) * 8192;
                wait_par(smb + MBAR_BYTE + (seq & 1) * 8, (seq >> 1) & 1);
                fragDdup<16>(buf, hdc + kc * 16 * 128, acc, col2, prow2);
                release_chunk(seq, smb, tid);
                ++seq;
            }
            gru_epi_dup(acc, hdc, hdn, col2, prow2);
        }
        float* tp = hdc; hdc = hdn; hdn = tp;
    }
    // after 128 swaps: hdc == HD0 (final h, dup), hdn == HD1 (dead)

    // -------- heads --------
    __syncthreads();
    {
        float* hfin = hdc;             // dup layout [k][128], == sm + 0
        float* sDW  = sm + 16384;      // [79][256] = 20224 fl, ends 36607
        float* zb   = sm + O_WI;       // z_cnn rows [r][128] = 8192 fl (WI dead)

        for (int i = tid; i < 64 * 128; i += THREADS) zb[i] = g_zc[(size_t)rb * 128 + i];
        for (int i = tid; i < 79 * 256; i += THREADS)
            sDW[i] = (i < 78 * 256) ? disw[i] : vw[i - 78 * 256];
        __syncthreads();

        for (int o = tid; o < 64 * 79; o += THREADS) {
            int r = o / 79, c = o % 79;
            const ull* wp = (const ull*)(sDW + c * 256);
            const ull* zr = (const ull*)(zb + r * 128);
            ull a2 = pk2(0.0f, 0.0f);
#pragma unroll 8
            for (int k = 0; k < 64; ++k) fma2(a2, zr[k], wp[k]);
            float lo, hi; upk2(a2, lo, hi);
            float acc = ((c < 78) ? disb[c] : vb[0]) + lo + hi;
            const float* wh = sDW + c * 256 + 128;
#pragma unroll 8
            for (int k = 0; k < 128; ++k)
                acc = fmaf(hfin[k * 128 + 2 * r], wh[k], acc);
            if (c < 78) out[(size_t)(rb + r) * 78 + c] = acc;
            else        out[(size_t)BATCH * 78 + rb + r] = acc;
        }
    }
}

// ============ CNN: 8 imgs/block (R8 verbatim) ============
__global__ void __launch_bounds__(128, 2)
conv_k(const float* __restrict__ cnn,
       const float* __restrict__ w1, const float* __restrict__ b1,
       const float* __restrict__ w2, const float* __restrict__ b2)
{
    extern __shared__ float sms[];
    float* sin_ = sms;
    float* sw1  = sin_ + 8 * 1728;
    float* sw2  = sw1 + 3888;
    float* sx1  = sw2 + 2048;
    const int tid = threadIdx.x;
    const int b0  = blockIdx.x * 8;

    for (int i = tid; i < 8 * 1728; i += 128) sin_[i] = cnn[(size_t)b0 * 1728 + i];
    for (int i = tid; i < 3888; i += 128) sw1[i] = w1[i];
    for (int i = tid; i < 2048; i += 128) sw2[i] = w2[i];
    __syncthreads();

    const int bb = tid >> 4, c = tid & 15;
    float acc[9];
    float bc = b1[c];
#pragma unroll
    for (int p = 0; p < 9; ++p) acc[p] = bc;
    for (int ky = 0; ky < 3; ++ky)
        for (int kx = 0; kx < 3; ++kx)
            for (int ic = 0; ic < 27; ++ic) {
                float w = sw1[c * 243 + ic * 9 + ky * 3 + kx];
#pragma unroll
                for (int i = 0; i < 3; ++i)
#pragma unroll
                    for (int jx = 0; jx < 3; ++jx)
                        acc[i*3+jx] = fmaf(sin_[((bb*8 + 2*i + ky)*8 + 2*jx + kx)*27 + ic], w, acc[i*3+jx]);
            }
#pragma unroll
    for (int p = 0; p < 9; ++p) sx1[(bb * 16 + c) * 9 + p] = fmaxf(acc[p], 0.0f);
    __syncthreads();

    float a2[2][4];
#pragma unroll
    for (int q = 0; q < 2; ++q) {
        float bcc = b2[c + 16 * q];
#pragma unroll
        for (int p = 0; p < 4; ++p) a2[q][p] = bcc;
    }
    for (int ci = 0; ci < 16; ++ci) {
        float xv[9];
#pragma unroll
        for (int p = 0; p < 9; ++p) xv[p] = sx1[(bb * 16 + ci) * 9 + p];
#pragma unroll
        for (int q = 0; q < 2; ++q) {
            int c2 = c + 16 * q;
#pragma unroll
            for (int ky = 0; ky < 2; ++ky)
#pragma unroll
                for (int kx = 0; kx < 2; ++kx) {
                    float w = sw2[(c2 * 16 + ci) * 4 + ky * 2 + kx];
#pragma unroll
                    for (int i = 0; i < 2; ++i)
#pragma unroll
                        for (int jx = 0; jx < 2; ++jx)
                            a2[q][i*2+jx] = fmaf(xv[(i+ky)*3 + (jx+kx)], w, a2[q][i*2+jx]);
                }
        }
    }
    float* outp = g_x2 + (size_t)(b0 + bb) * 128;
#pragma unroll
    for (int q = 0; q < 2; ++q)
#pragma unroll
        for (int p = 0; p < 4; ++p)
            outp[(c + 16 * q) * 4 + p] = fmaxf(a2[q][p], 0.0f);
}

// ============ fc: smem-tiled (R8 verbatim) ============
__global__ void __launch_bounds__(512, 1)
fc_k(const float* __restrict__ W, const float* __restrict__ bias)
{
    extern __shared__ float s[];
    float* xs = s;            // [128 rows][128 k]
    float* wt = s + 16384;    // [128 k][128 j]
    const int tid = threadIdx.x;
    const int b0  = blockIdx.x * 128;

    for (int i = tid; i < 16384; i += 512) xs[i] = g_x2[(size_t)b0 * 128 + i];
    for (int i = tid; i < 16384; i += 512) {
        int k = i >> 7, j = i & 127;
        wt[i] = W[(size_t)j * 128 + k];
    }
    __syncthreads();

    const int j  = tid & 127;
    const int rg = tid >> 7;
    float acc[32];
    float bj = bias[j];
#pragma unroll
    for (int r = 0; r < 32; ++r) acc[r] = bj;

#pragma unroll 1
    for (int kb = 0; kb < 16; ++kb) {
        float w8[8];
#pragma unroll
        for (int kk = 0; kk < 8; ++kk) w8[kk] = wt[(kb * 8 + kk) * 128 + j];
#pragma unroll
        for (int r = 0; r < 32; ++r) {
            const float* xr = xs + (rg * 32 + r) * 128 + kb * 8;
            float4 a = *(const float4*)(xr);
            float4 b = *(const float4*)(xr + 4);
            float t = acc[r];
            t = fmaf(a.x, w8[0], t); t = fmaf(a.y, w8[1], t);
            t = fmaf(a.z, w8[2], t); t = fmaf(a.w, w8[3], t);
            t = fmaf(b.x, w8[4], t); t = fmaf(b.y, w8[5], t);
            t = fmaf(b.z, w8[6], t); t = fmaf(b.w, w8[7], t);
            acc[r] = t;
        }
    }
#pragma unroll
    for (int r = 0; r < 32; ++r)
        g_zc[(size_t)(b0 + rg * 32 + r) * 128 + j] = fmaxf(acc[r], 0.0f);
}

extern "C" void kernel_launch(void* const* d_in, const int* in_sizes, int n_in,
                              void* d_out, int out_size)
{
    const float* cnn  = (const float*)d_in[0];
    const float* lin  = (const float*)d_in[1];
    const float* c1w  = (const float*)d_in[2];
    const float* c1b  = (const float*)d_in[3];
    const float* c2w  = (const float*)d_in[4];
    const float* c2b  = (const float*)d_in[5];
    const float* fcw  = (const float*)d_in[6];
    const float* fcb  = (const float*)d_in[7];
    const float* eWih = (const float*)d_in[8];
    const float* eWhh = (const float*)d_in[9];
    const float* ebih = (const float*)d_in[10];
    const float* ebhh = (const float*)d_in[11];
    const float* dWih = (const float*)d_in[12];
    const float* dWhh = (const float*)d_in[13];
    const float* dbih = (const float*)d_in[14];
    const float* dbhh = (const float*)d_in[15];
    const float* disw = (const float*)d_in[16];
    const float* disb = (const float*)d_in[17];
    const float* vw   = (const float*)d_in[18];
    const float* vb   = (const float*)d_in[19];
    float* out = (float*)d_out;

    cudaFuncSetAttribute(conv_k,  cudaFuncAttributeMaxDynamicSharedMemorySize, CONV_SMEM);
    cudaFuncSetAttribute(fc_k,    cudaFuncAttributeMaxDynamicSharedMemorySize, FC_SMEM);
    cudaFuncSetAttribute(recur_k, cudaFuncAttributeMaxDynamicSharedMemorySize, SMEM_BYTES);

    wt_k<<<(128*384 + 128*512 + 255) / 256, 256>>>(eWhh, dWih, dWhh);
    conv_k<<<BATCH / 8, 128, CONV_SMEM>>>(cnn, c1w, c1b, c2w, c2b);
    fc_k<<<BATCH / 128, 512, FC_SMEM>>>(fcw, fcb);

    recur_k<<<NCTA, THREADS, SMEM_BYTES>>>(lin, eWih,
                                           ebih, ebhh, dbih, dbhh,
                                           disw, disb, vw, vb, out);
}

// round 17
// speedup vs baseline: 1.4542x; 1.4542x over previous
#include <cuda_runtime.h>
#include <cstdint>

typedef unsigned long long ull;

#define BATCH 8192
#define TSTEPS 64
#define NCTA 128
#define NCONV 20
#define THREADS 512

__device__ float g_zc[BATCH * 128];
__device__ float g_eWT[128 * 384];    // enc Whh^T [k][j]  (r|z|n)
__device__ float g_dWT2[128 * 512];   // dec t>=1: [k][ (Wih+Whh)_rz | Wih_n | Whh_n ]
__device__ float g_dW0[128 * 512];    // dec t==0: [k][ Whh_rz | 0 | Whh_n ]
__device__ int   g_done;              // conv-CTA completion counter

// smem layout (float offsets) — identical to R8
constexpr int O_H0   = 0;        // h ping [k=128][row=64]
constexpr int O_H1   = 8192;     // h pong
constexpr int O_BUF0 = 16384;    // chunk buf 0 (12288 fl = 48KB)
constexpr int O_WI   = 40960;    // enc Wih^T [29][384] = 11136
constexpr int O_X    = 52096;    // x_t^T [29][64] = 1856
constexpr int O_B    = 53952;    // fused biases: enc 512 + dec 512
constexpr int MBAR_BYTE  = 55488 * 4;
constexpr int SMEM_BYTES = MBAR_BYTE + 32;
constexpr int NSEQ = 512 + 1024;         // enc 64*2*4, dec 64*2*8

__device__ __forceinline__ ull pk2(float a, float b) {
    ull r; asm("mov.b64 %0, {%1,%2};" : "=l"(r) : "f"(a), "f"(b)); return r;
}
__device__ __forceinline__ void upk2(ull v, float& a, float& b) {
    asm("mov.b64 {%0,%1}, %2;" : "=f"(a), "=f"(b) : "l"(v));
}
__device__ __forceinline__ void fma2(ull& d, ull a, ull b) {
    asm("fma.rn.f32x2 %0, %1, %2, %0;" : "+l"(d) : "l"(a), "l"(b));
}
__device__ __forceinline__ float sigf(float x)     { return 1.0f / (1.0f + __expf(-x)); }
__device__ __forceinline__ float tanhfast(float x) { return 2.0f / (1.0f + __expf(-2.0f * x)) - 1.0f; }
__device__ __forceinline__ uint32_t smem_u32(const void* p) {
    uint32_t a;
    asm("{ .reg .u64 t; cvta.to.shared.u64 t, %1; cvt.u32.u64 %0, t; }" : "=r"(a) : "l"(p));
    return a;
}
__device__ __forceinline__ void mbar_init(uint32_t bar, uint32_t cnt) {
    asm volatile("mbarrier.init.shared.b64 [%0], %1;" :: "r"(bar), "r"(cnt) : "memory");
}
__device__ __forceinline__ void mbar_arrive(uint32_t bar) {
    asm volatile("mbarrier.arrive.release.cta.shared::cta.b64 _, [%0];" :: "r"(bar) : "memory");
}
__device__ __forceinline__ void wait_par(uint32_t bar, uint32_t parity) {
    asm volatile(
        "{\n\t.reg .pred P;\n\t"
        "WL_%=:\n\t"
        "mbarrier.try_wait.parity.acquire.cta.shared::cta.b64 P, [%0], %1, 0x989680;\n\t"
        "@P bra.uni WD_%=;\n\t"
        "bra.uni WL_%=;\n\t"
        "WD_%=:\n\t}"
        :: "r"(bar), "r"(parity) : "memory");
}
// seq -> (src, bytes): enc s<512: 48KB from g_eWT; dec: 32KB from g_dW0/g_dWT2
__device__ __forceinline__ void issue_chunk(int s, uint32_t smb) {
    uint32_t dst = smb + (uint32_t)(O_BUF0 + (s & 1) * 12288) * 4;
    uint32_t bar = smb + MBAR_BYTE + (s & 1) * 8;
    const float* src;
    uint32_t bytes;
    if (s < 512) {
        src = g_eWT + (size_t)(s & 3) * 32 * 384;
        bytes = 49152;
    } else {
        int d = s - 512;
        int t = d >> 4;
        src = (t == 0 ? g_dW0 : g_dWT2) + (size_t)(d & 7) * 16 * 512;
        bytes = 32768;
    }
    asm volatile("mbarrier.arrive.expect_tx.shared.b64 _, [%0], %1;"
                 :: "r"(bar), "r"(bytes) : "memory");
    asm volatile("cp.async.bulk.shared::cluster.global.mbarrier::complete_tx::bytes "
                 "[%0], [%1], %2, [%3];"
                 :: "r"(dst), "l"(src), "r"(bytes), "r"(bar) : "memory");
}
__device__ __forceinline__ void release_chunk(int s, uint32_t smb, int tid) {
    uint32_t ebar = smb + MBAR_BYTE + 16 + (s & 1) * 8;
    if ((tid & 31) == 0) mbar_arrive(ebar);
    if (tid == 0 && s + 2 < NSEQ) {
        wait_par(ebar, (uint32_t)((s >> 1) & 1));
        issue_chunk(s + 2, smb);
    }
}

// enc fragment (R8 verbatim)
template <int KN, int WW, int S2>
__device__ __forceinline__ void fragE(const float* __restrict__ w,
                                      const float* __restrict__ op,
                                      ull (&acc)[4][4], int col2, int prow)
{
#pragma unroll 8
    for (int k = 0; k < KN; ++k) {
        float4 hv = *(const float4*)(op + k * 64 + prow);
        ull h0 = pk2(hv.x, hv.x), h1 = pk2(hv.y, hv.y);
        ull h2 = pk2(hv.z, hv.z), h3 = pk2(hv.w, hv.w);
        ull w0 = *(const ull*)(w + k * WW + col2);
        ull w1 = *(const ull*)(w + k * WW + 128 + col2);
        ull w2 = *(const ull*)(w + k * WW + 256 + col2);
        fma2(acc[0][0], h0, w0); fma2(acc[0][1], h1, w0);
        fma2(acc[0][2], h2, w0); fma2(acc[0][3], h3, w0);
        fma2(acc[1][0], h0, w1); fma2(acc[1][1], h1, w1);
        fma2(acc[1][2], h2, w1); fma2(acc[1][3], h3, w1);
        fma2(acc[S2][0], h0, w2); fma2(acc[S2][1], h1, w2);
        fma2(acc[S2][2], h2, w2); fma2(acc[S2][3], h3, w2);
    }
}
// dec fragment (R8 verbatim)
template <int KN>
__device__ __forceinline__ void fragD(const float* __restrict__ w,
                                      const float* __restrict__ op,
                                      ull (&acc)[4][4], int col2, int prow)
{
#pragma unroll 8
    for (int k = 0; k < KN; ++k) {
        float4 hv = *(const float4*)(op + k * 64 + prow);
        ull h0 = pk2(hv.x, hv.x), h1 = pk2(hv.y, hv.y);
        ull h2 = pk2(hv.z, hv.z), h3 = pk2(hv.w, hv.w);
#pragma unroll
        for (int s = 0; s < 4; ++s) {
            ull wv = *(const ull*)(w + k * 512 + s * 128 + col2);
            fma2(acc[s][0], h0, wv); fma2(acc[s][1], h1, wv);
            fma2(acc[s][2], h2, wv); fma2(acc[s][3], h3, wv);
        }
    }
}
// epilogue (R8 verbatim)
__device__ __forceinline__ void gru_epi(ull (&acc)[4][4], const float* __restrict__ hc,
                                        float* __restrict__ hn, int j, int prow)
{
#pragma unroll
    for (int rr = 0; rr < 4; ++rr) {
        int r = prow + rr;
        float r0, r1, z0, z1, xn0, xn1, hn0, hn1;
        upk2(acc[0][rr], r0, r1); upk2(acc[1][rr], z0, z1);
        upk2(acc[2][rr], xn0, xn1); upk2(acc[3][rr], hn0, hn1);
        float rg0 = sigf(r0), rg1 = sigf(r1);
        float zg0 = sigf(z0), zg1 = sigf(z1);
        float n0 = tanhfast(xn0 + rg0 * hn0), n1 = tanhfast(xn1 + rg1 * hn1);
        float hp0 = hc[j * 64 + r], hp1 = hc[(j + 1) * 64 + r];
        hn[j * 64 + r]       = (1.0f - zg0) * n0 + zg0 * hp0;
        hn[(j + 1) * 64 + r] = (1.0f - zg1) * n1 + zg1 * hp1;
    }
}

// one-shot weight prep (R8 verbatim) + g_done reset
__global__ void wt_k(const float* __restrict__ eWhh,
                     const float* __restrict__ dWih, const float* __restrict__ dWhh)
{
    int i = blockIdx.x * 256 + threadIdx.x;
    if (i == 0) g_done = 0;
    if (i < 128 * 384) {
        int k = i / 384, j = i % 384;
        g_eWT[i] = eWhh[(size_t)j * 128 + k];
    } else if (i < 128 * 384 + 128 * 512) {
        int e = i - 128 * 384;
        int k = e / 512, j = e % 512;
        float v, v0;
        if (j < 256)      { v = dWih[(size_t)j * 128 + k] + dWhh[(size_t)j * 128 + k];
                            v0 = dWhh[(size_t)j * 128 + k]; }
        else if (j < 384) { v = dWih[(size_t)j * 128 + k];  v0 = 0.0f; }
        else              { v = dWhh[(size_t)(j - 128) * 128 + k];
                            v0 = dWhh[(size_t)(j - 128) * 128 + k]; }
        g_dWT2[e] = v;
        g_dW0[e]  = v0;
    }
}

// ============ conv+fc side-CTA: processes image groups of 16 ============
__device__ void conv_cta(int cid, float* sm, const float* __restrict__ cnn,
                         const float* __restrict__ w1, const float* __restrict__ b1,
                         const float* __restrict__ w2, const float* __restrict__ b2,
                         const float* __restrict__ fcw, const float* __restrict__ fcb)
{
    float* sin_ = sm;                  // 16*1728 = 27648
    float* sw1  = sin_ + 27648;        // 3888
    float* sw2  = sw1 + 3888;          // 2048
    float* sx1  = sw2 + 2048;          // 16*144 = 2304
    float* sX2  = sx1 + 2304;          // 16*128 = 2048
    float* sWT  = sX2 + 2048;          // fc_w^T [k][j] = 16384  (total 54320 fl)
    const int tid = threadIdx.x;

    for (int i = tid; i < 3888; i += THREADS) sw1[i] = w1[i];
    for (int i = tid; i < 2048; i += THREADS) sw2[i] = w2[i];
    for (int i = tid; i < 16384; i += THREADS) {
        int k = i >> 7, j = i & 127;
        sWT[i] = fcw[(size_t)j * 128 + k];
    }

    for (int g = cid; g < BATCH / 16; g += NCONV) {
        const int b0 = g * 16;
        __syncthreads();   // previous iteration's readers done
        for (int i = tid; i < 16 * 1728; i += THREADS)
            sin_[i] = cnn[(size_t)b0 * 1728 + i];
        __syncthreads();

        if (tid < 256) {
            const int bb = tid >> 4, c = tid & 15;
            // conv1: 27->16, 3x3, stride 2, relu
            float acc[9];
            float bc = b1[c];
#pragma unroll
            for (int p = 0; p < 9; ++p) acc[p] = bc;
            for (int ky = 0; ky < 3; ++ky)
                for (int kx = 0; kx < 3; ++kx)
                    for (int ic = 0; ic < 27; ++ic) {
                        float w = sw1[c * 243 + ic * 9 + ky * 3 + kx];
#pragma unroll
                        for (int i = 0; i < 3; ++i)
#pragma unroll
                            for (int jx = 0; jx < 3; ++jx)
                                acc[i*3+jx] = fmaf(sin_[((bb*8 + 2*i + ky)*8 + 2*jx + kx)*27 + ic],
                                                   w, acc[i*3+jx]);
                    }
#pragma unroll
            for (int p = 0; p < 9; ++p) sx1[(bb * 16 + c) * 9 + p] = fmaxf(acc[p], 0.0f);
        }
        __syncthreads();
        if (tid < 256) {
            const int bb = tid >> 4, c = tid & 15;
            // conv2: 16->32, 2x2, stride 1, relu; write x2 rows to sX2
            float a2[2][4];
#pragma unroll
            for (int q = 0; q < 2; ++q) {
                float bcc = b2[c + 16 * q];
#pragma unroll
                for (int p = 0; p < 4; ++p) a2[q][p] = bcc;
            }
            for (int ci = 0; ci < 16; ++ci) {
                float xv[9];
#pragma unroll
                for (int p = 0; p < 9; ++p) xv[p] = sx1[(bb * 16 + ci) * 9 + p];
#pragma unroll
                for (int q = 0; q < 2; ++q) {
                    int c2 = c + 16 * q;
#pragma unroll
                    for (int ky = 0; ky < 2; ++ky)
#pragma unroll
                        for (int kx = 0; kx < 2; ++kx) {
                            float w = sw2[(c2 * 16 + ci) * 4 + ky * 2 + kx];
#pragma unroll
                            for (int i = 0; i < 2; ++i)
#pragma unroll
                                for (int jx = 0; jx < 2; ++jx)
                                    a2[q][i*2+jx] = fmaf(xv[(i+ky)*3 + (jx+kx)], w, a2[q][i*2+jx]);
                        }
                }
            }
#pragma unroll
            for (int q = 0; q < 2; ++q)
#pragma unroll
                for (int p = 0; p < 4; ++p)
                    sX2[bb * 128 + (c + 16 * q) * 4 + p] = fmaxf(a2[q][p], 0.0f);
        }
        __syncthreads();
        // fc: 16 rows x 128 outputs, relu, straight to g_zc
        {
            const int j = tid & 127, rq = tid >> 7;   // rq 0..3
#pragma unroll
            for (int rr = 0; rr < 4; ++rr) {
                int r = rq * 4 + rr;
                float acc = fcb[j];
                const float* xr = sX2 + r * 128;
#pragma unroll 8
                for (int k = 0; k < 128; ++k) acc = fmaf(xr[k], sWT[k * 128 + j], acc);
                g_zc[(size_t)(b0 + r) * 128 + j] = fmaxf(acc, 0.0f);
            }
        }
    }
    __threadfence();
    __syncthreads();
    if (tid == 0) atomicAdd(&g_done, 1);
}

// ============ persistent kernel: 128 recur CTAs + 20 conv CTAs ============
__global__ void __launch_bounds__(THREADS, 1)
recur_k(const float* __restrict__ lin, const float* __restrict__ eWih,
        const float* __restrict__ ebih, const float* __restrict__ ebhh,
        const float* __restrict__ dbih, const float* __restrict__ dbhh,
        const float* __restrict__ disw, const float* __restrict__ disb,
        const float* __restrict__ vw,   const float* __restrict__ vb,
        const float* __restrict__ cnn,
        const float* __restrict__ c1w, const float* __restrict__ c1b,
        const float* __restrict__ c2w, const float* __restrict__ c2b,
        const float* __restrict__ fcw, const float* __restrict__ fcb,
        float* __restrict__ out)
{
    extern __shared__ float sm[];

    if (blockIdx.x >= NCTA) {   // side CTAs: conv+fc on otherwise-idle SMs
        conv_cta(blockIdx.x - NCTA, sm, cnn, c1w, c1b, c2w, c2b, fcw, fcb);
        return;
    }

    const uint32_t smb = smem_u32(sm);
    const int tid  = threadIdx.x;
    const int rb   = blockIdx.x * 64;
    const int rg   = tid & 7;          // row group of 4
    const int col2 = 2 * (tid >> 3);   // feature pair

    for (int i = tid; i < 8192; i += THREADS) sm[O_H0 + i] = 0.0f;
    for (int i = tid; i < 128; i += THREADS) {
        sm[O_B + i]       = ebih[i]       + ebhh[i];
        sm[O_B + 128 + i] = ebih[128 + i] + ebhh[128 + i];
        sm[O_B + 256 + i] = ebih[256 + i];
        sm[O_B + 384 + i] = ebhh[256 + i];
        sm[O_B + 512 + i] = dbih[i]       + dbhh[i];
        sm[O_B + 640 + i] = dbih[128 + i] + dbhh[128 + i];
        sm[O_B + 768 + i] = dbih[256 + i];
        sm[O_B + 896 + i] = dbhh[256 + i];
    }
    for (int i = tid; i < 29 * 384; i += THREADS) {
        int k = i / 384, j = i % 384;
        sm[O_WI + k * 384 + j] = eWih[(size_t)j * 29 + k];
    }
    if (tid == 0) {
        mbar_init(smb + MBAR_BYTE,      1);   // full0
        mbar_init(smb + MBAR_BYTE + 8,  1);   // full1
        mbar_init(smb + MBAR_BYTE + 16, 16);  // empty0
        mbar_init(smb + MBAR_BYTE + 24, 16);  // empty1
    }
    __syncthreads();
    if (tid == 0) {
        asm volatile("fence.proxy.async.shared::cta;" ::: "memory");
        issue_chunk(0, smb); issue_chunk(1, smb);
    }

    float* hc = sm + O_H0;
    float* hn = sm + O_H1;
    int seq = 0;

    // -------- encoder (R8 verbatim) --------
    for (int t = 0; t < TSTEPS; ++t) {
        __syncthreads();
        for (int i = tid; i < 64 * 29; i += THREADS) {
            int r = i / 29, k = i % 29;
            sm[O_X + k * 64 + r] = lin[(size_t)(rb + r) * 1856 + (size_t)t * 29 + k];
        }
        __syncthreads();
#pragma unroll 1
        for (int pass = 0; pass < 2; ++pass) {
            const int prow = pass * 32 + rg * 4;
            ull acc[4][4];
#pragma unroll
            for (int s = 0; s < 4; ++s) {
                ull bv = *(const ull*)(sm + O_B + s * 128 + col2);
#pragma unroll
                for (int rr = 0; rr < 4; ++rr) acc[s][rr] = bv;
            }
            fragE<29, 384, 2>(sm + O_WI, sm + O_X, acc, col2, prow);
#pragma unroll 1
            for (int kc = 0; kc < 4; ++kc) {
                const float* buf = sm + O_BUF0 + (seq & 1) * 12288;
                wait_par(smb + MBAR_BYTE + (seq & 1) * 8, (seq >> 1) & 1);
                fragE<32, 384, 3>(buf, hc + kc * 32 * 64, acc, col2, prow);
                release_chunk(seq, smb, tid);
                ++seq;
            }
            gru_epi(acc, hc, hn, col2, prow);
        }
        float* tp = hc; hc = hn; hn = tp;
    }

    // -------- decoder (R8 verbatim) --------
    for (int t = 0; t < TSTEPS; ++t) {
        __syncthreads();
#pragma unroll 1
        for (int pass = 0; pass < 2; ++pass) {
            const int prow = pass * 32 + rg * 4;
            ull acc[4][4];
#pragma unroll
            for (int s = 0; s < 4; ++s) {
                ull bv = *(const ull*)(sm + O_B + 512 + s * 128 + col2);
#pragma unroll
                for (int rr = 0; rr < 4; ++rr) acc[s][rr] = bv;
            }
#pragma unroll 1
            for (int kc = 0; kc < 8; ++kc) {
                const float* buf = sm + O_BUF0 + (seq & 1) * 12288;
                wait_par(smb + MBAR_BYTE + (seq & 1) * 8, (seq >> 1) & 1);
                fragD<16>(buf, hc + kc * 16 * 64, acc, col2, prow);
                release_chunk(seq, smb, tid);
                ++seq;
            }
            gru_epi(acc, hc, hn, col2, prow);
        }
        float* tp = hc; hc = hn; hn = tp;
    }

    // -------- heads (wait for conv CTAs, then R8 verbatim) --------
    if (tid == 0) {
        while (atomicAdd(&g_done, 0) < NCONV) {}
    }
    __syncthreads();
    {
        float* hfin = hc;
        float* zb   = hn;
        float* sDW  = sm + O_BUF0;     // [79][256]
        float* sHT  = sm + O_WI;       // [64][128]

        for (int i = tid; i < 64 * 128; i += THREADS) zb[i] = g_zc[(size_t)rb * 128 + i];
        for (int i = tid; i < 79 * 256; i += THREADS)
            sDW[i] = (i < 78 * 256) ? disw[i] : vw[i - 78 * 256];
        for (int i = tid; i < 64 * 128; i += THREADS) {
            int r = i >> 7, k = i & 127;
            sHT[i] = hfin[k * 64 + r];
        }
        __syncthreads();

        for (int o = tid; o < 64 * 79; o += THREADS) {
            int r = o / 79, c = o % 79;
            const ull* wp = (const ull*)(sDW + c * 256);
            const ull* zr = (const ull*)(zb + r * 128);
            const ull* hr = (const ull*)(sHT + r * 128);
            ull a2 = pk2(0.0f, 0.0f);
#pragma unroll 8
            for (int k = 0; k < 64; ++k) fma2(a2, zr[k], wp[k]);
#pragma unroll 8
            for (int k = 0; k < 64; ++k) fma2(a2, hr[k], wp[64 + k]);
            float lo, hi; upk2(a2, lo, hi);
            float acc = ((c < 78) ? disb[c] : vb[0]) + lo + hi;
            if (c < 78) out[(size_t)(rb + r) * 78 + c] = acc;
            else        out[(size_t)BATCH * 78 + rb + r] = acc;
        }
    }
}

extern "C" void kernel_launch(void* const* d_in, const int* in_sizes, int n_in,
                              void* d_out, int out_size)
{
    const float* cnn  = (const float*)d_in[0];
    const float* lin  = (const float*)d_in[1];
    const float* c1w  = (const float*)d_in[2];
    const float* c1b  = (const float*)d_in[3];
    const float* c2w  = (const float*)d_in[4];
    const float* c2b  = (const float*)d_in[5];
    const float* fcw  = (const float*)d_in[6];
    const float* fcb  = (const float*)d_in[7];
    const float* eWih = (const float*)d_in[8];
    const float* eWhh = (const float*)d_in[9];
    const float* ebih = (const float*)d_in[10];
    const float* ebhh = (const float*)d_in[11];
    const float* dWih = (const float*)d_in[12];
    const float* dWhh = (const float*)d_in[13];
    const float* dbih = (const float*)d_in[14];
    const float* dbhh = (const float*)d_in[15];
    const float* disw = (const float*)d_in[16];
    const float* disb = (const float*)d_in[17];
    const float* vw   = (const float*)d_in[18];
    const float* vb   = (const float*)d_in[19];
    float* out = (float*)d_out;

    cudaFuncSetAttribute(recur_k, cudaFuncAttributeMaxDynamicSharedMemorySize, SMEM_BYTES);

    wt_k<<<(128*384 + 128*512 + 255) / 256, 256>>>(eWhh, dWih, dWhh);

    recur_k<<<NCTA + NCONV, THREADS, SMEM_BYTES>>>(lin, eWih,
                                                   ebih, ebhh, dbih, dbhh,
                                                   disw, disb, vw, vb,
                                                   cnn, c1w, c1b, c2w, c2b, fcw, fcb,
                                                   out);
}